// round 7
// baseline (speedup 1.0000x reference)
#include <cuda_runtime.h>
#include <cuda_bf16.h>
#include <cstdint>

#define NPTS 8192
#define DIM  128

#define S1f 0.043307086614173228f      // 5.5/127
#define S2f (S1f / 127.0f)

// ---------------- scratch -----------------------------------------------------
static __device__ char   g_q1[(size_t)NPTS * DIM];
static __device__ char   g_q2[(size_t)NPTS * DIM];
static __device__ float  g_sq[NPTS];                      // exact fp32 row norms
static __device__ float2 g_top[(size_t)NPTS * 16 * 6];    // per-row 16 chunk lists

// ---------------- helpers ------------------------------------------------------
__device__ __forceinline__ uint32_t smem_u32(const void* p) {
    uint32_t a;
    asm("{ .reg .u64 t; cvta.to.shared.u64 t, %1; cvt.u32.u64 %0, t; }"
        : "=r"(a) : "l"(p));
    return a;
}
__device__ __forceinline__ void cp16(uint32_t dst, const void* src) {
    asm volatile("cp.async.cg.shared.global [%0], [%1], 16;"
                 :: "r"(dst), "l"(src) : "memory");
}
#define CP_COMMIT() asm volatile("cp.async.commit_group;" ::: "memory")

__device__ __forceinline__ void imma(int* c, const uint32_t* a, uint32_t b0, uint32_t b1) {
    asm volatile("mma.sync.aligned.m16n8k32.row.col.s32.s8.s8.s32 "
        "{%0,%1,%2,%3}, {%4,%5,%6,%7}, {%8,%9}, {%0,%1,%2,%3};"
        : "+r"(c[0]), "+r"(c[1]), "+r"(c[2]), "+r"(c[3])
        : "r"(a[0]), "r"(a[1]), "r"(a[2]), "r"(a[3]), "r"(b0), "r"(b1));
}

// top-6 insert (value + index), ascending
__device__ __forceinline__ void ins6(float v, int idx, float* nb, int* ni) {
    if (v < nb[5]) {
        nb[5] = v; ni[5] = idx;
        #pragma unroll
        for (int k = 5; k > 0; k--) {
            if (nb[k] < nb[k - 1]) {
                float tv = nb[k]; nb[k] = nb[k - 1]; nb[k - 1] = tv;
                int   ti = ni[k]; ni[k] = ni[k - 1]; ni[k - 1] = ti;
            }
        }
    }
}

// ---------------- kernel 1: 2-digit int8 quantize + exact row norms -----------
__global__ __launch_bounds__(256) void prep_kernel(const float* __restrict__ f) {
    int wid = threadIdx.x >> 5, lane = threadIdx.x & 31;
    int row = blockIdx.x * 8 + wid;
    float4 v = ((const float4*)f)[row * 32 + lane];
    float s = v.x * v.x + v.y * v.y + v.z * v.z + v.w * v.w;
    float inv1 = 1.0f / S1f, inv2 = 1.0f / S2f;
    float xs[4] = {v.x, v.y, v.z, v.w};
    char q1c[4], q2c[4];
    #pragma unroll
    for (int i = 0; i < 4; i++) {
        int q1 = __float2int_rn(xs[i] * inv1);
        q1 = max(-127, min(127, q1));
        float r = xs[i] - S1f * (float)q1;
        int q2 = __float2int_rn(r * inv2);
        q2 = max(-127, min(127, q2));
        q1c[i] = (char)q1; q2c[i] = (char)q2;
    }
    *(char4*)(g_q1 + (size_t)row * DIM + lane * 4) = make_char4(q1c[0], q1c[1], q1c[2], q1c[3]);
    *(char4*)(g_q2 + (size_t)row * DIM + lane * 4) = make_char4(q2c[0], q2c[1], q2c[2], q2c[3]);
    #pragma unroll
    for (int o = 16; o; o >>= 1) s += __shfl_xor_sync(0xffffffffu, s, o);
    if (lane == 0) g_sq[row] = s;
}

// ---------------- kernel 2: 128-row x 512-col strip, row top-6 in regs --------
#define AROW   144                         // 128 data + 16 pad
#define SM_A1  0                           // 128 x 144
#define SM_A2  18432
#define SM_BB  36864                       // 2 bufs x 2 digits x (64 x 144)
#define SM_STG 73728                       // 128 x 66 words = 33792
#define SM_SQR 107520                      // 128 floats
#define SM_SQC 108032                      // 64 floats
#define SM_TOTAL 108288
#define SM_LST SM_STG                      // final list staging reuses STG

__global__ __launch_bounds__(256, 2)
void gemm_topk_kernel(float* __restrict__ out) {
    extern __shared__ char smem_[];
    char* sm = smem_;
    uint32_t sbase = smem_u32(sm);
    int tid = threadIdx.x;
    int bx = blockIdx.x;                   // col chunk 0..15 (512 cols)
    int by = blockIdx.y;                   // row block 0..63
    int row0 = by * 128, col0 = bx * 512;

    if (tid < 128) ((float*)(sm + SM_SQR))[tid] = g_sq[row0 + tid];

    // ---- A fill (resident all 8 tiles): 2048 cp16 ----
    {
        const char* a1 = g_q1 + (size_t)row0 * DIM;
        const char* a2 = g_q2 + (size_t)row0 * DIM;
        #pragma unroll
        for (int it = 0; it < 8; it++) {
            int idx = tid + it * 256;
            int dig = idx >> 10, rem = idx & 1023;
            int row = rem >> 3, ch = rem & 7;
            uint32_t dst = sbase + (dig ? SM_A2 : SM_A1) + row * AROW + ch * 16;
            cp16(dst, (dig ? a2 : a1) + row * DIM + ch * 16);
        }
        CP_COMMIT();
    }
    // ---- B tile 0 fill: 1024 cp16 ----
    {
        const char* b1 = g_q1 + (size_t)col0 * DIM;
        const char* b2 = g_q2 + (size_t)col0 * DIM;
        #pragma unroll
        for (int it = 0; it < 4; it++) {
            int idx = tid + it * 256;
            int dig = idx >> 9, rem = idx & 511;
            int row = rem >> 3, ch = rem & 7;
            uint32_t dst = sbase + SM_BB + dig * 9216 + row * AROW + ch * 16;
            cp16(dst, (dig ? b2 : b1) + row * DIM + ch * 16);
        }
        CP_COMMIT();
    }

    // ---- zero-fill out slice (overlaps cp.async): 128 rows x 512 cols ----
    {
        float4 z = make_float4(0.f, 0.f, 0.f, 0.f);
        #pragma unroll
        for (int i = 0; i < 64; i++) {
            int idx = tid + i * 256;           // 0..16383
            int r = idx >> 7, c = idx & 127;
            ((float4*)out)[(size_t)(row0 + r) * 2048 + (col0 >> 2) + c] = z;
        }
    }

    int wq = tid >> 5, l = tid & 31;
    int wm = wq & 3, wn = wq >> 2;            // 4x2 warps: 32-row x 32-col
    int tg = l >> 2, tk = l & 3;
    uint32_t aoff = (uint32_t)((wm * 32 + tg) * AROW + tk * 4);
    uint32_t boff = (uint32_t)((wn * 32 + tg) * AROW + tk * 4);

    float nb[6]; int ni[6];
    #pragma unroll
    for (int k = 0; k < 6; k++) { nb[k] = 3.0e38f; ni[k] = 0; }

    #pragma unroll 1
    for (int t = 0; t < 8; t++) {
        // prefetch next B tile
        if (t < 7) {
            const char* b1 = g_q1 + (size_t)(col0 + (t + 1) * 64) * DIM;
            const char* b2 = g_q2 + (size_t)(col0 + (t + 1) * 64) * DIM;
            uint32_t bufb = sbase + SM_BB + ((t + 1) & 1) * 18432;
            #pragma unroll
            for (int it = 0; it < 4; it++) {
                int idx = tid + it * 256;
                int dig = idx >> 9, rem = idx & 511;
                int row = rem >> 3, ch = rem & 7;
                cp16(bufb + dig * 9216 + row * AROW + ch * 16,
                     (dig ? b2 : b1) + row * DIM + ch * 16);
            }
            CP_COMMIT();
        }
        if (tid < 64) ((float*)(sm + SM_SQC))[tid] = g_sq[col0 + t * 64 + tid];
        if (t < 7) asm volatile("cp.async.wait_group 1;" ::: "memory");
        else       asm volatile("cp.async.wait_group 0;" ::: "memory");
        __syncthreads();

        // ---- IMMA: 3 chains x 4 k-steps ----
        uint32_t A1 = sbase + SM_A1, A2 = sbase + SM_A2;
        uint32_t B1 = sbase + SM_BB + (t & 1) * 18432;
        uint32_t B2 = B1 + 9216;

        int accP[2][4][4], accX[2][4][4];
        #pragma unroll
        for (int mi = 0; mi < 2; mi++)
            #pragma unroll
            for (int ng = 0; ng < 4; ng++)
                #pragma unroll
                for (int q = 0; q < 4; q++) { accP[mi][ng][q] = 0; accX[mi][ng][q] = 0; }

        #pragma unroll
        for (int chain = 0; chain < 3; chain++) {
            uint32_t Abase = (chain == 2 ? A2 : A1) + aoff;
            uint32_t Bbase = (chain == 1 ? B2 : B1) + boff;
            int (*acc)[4][4] = (chain == 0) ? accP : accX;
            #pragma unroll
            for (int ks = 0; ks < 4; ks++) {
                uint32_t kb = ks * 32;
                uint32_t a[2][4];
                #pragma unroll
                for (int mi = 0; mi < 2; mi++) {
                    uint32_t base = Abase + mi * 16 * AROW + kb - sbase;
                    a[mi][0] = *(const uint32_t*)(sm + base);
                    a[mi][1] = *(const uint32_t*)(sm + base + 8 * AROW);
                    a[mi][2] = *(const uint32_t*)(sm + base + 16);
                    a[mi][3] = *(const uint32_t*)(sm + base + 8 * AROW + 16);
                }
                uint32_t bb[4][2];
                #pragma unroll
                for (int ng = 0; ng < 4; ng++) {
                    uint32_t base = Bbase + ng * 8 * AROW + kb - sbase;
                    bb[ng][0] = *(const uint32_t*)(sm + base);
                    bb[ng][1] = *(const uint32_t*)(sm + base + 16);
                }
                #pragma unroll
                for (int mi = 0; mi < 2; mi++)
                    #pragma unroll
                    for (int ng = 0; ng < 4; ng++)
                        imma(acc[mi][ng], a[mi], bb[ng][0], bb[ng][1]);
            }
        }

        // ---- stage s = sq_col - 2*dot ----
        {
            const float* sqc = (const float*)(sm + SM_SQC);
            const float c11 = S1f * S1f, c12 = S1f * S2f;
            #pragma unroll
            for (int mi = 0; mi < 2; mi++) {
                int r0 = wm * 32 + mi * 16 + tg;
                #pragma unroll
                for (int ng = 0; ng < 4; ng++) {
                    int col = wn * 32 + ng * 8 + 2 * tk;
                    float d0 = c11 * (float)accP[mi][ng][0] + c12 * (float)accX[mi][ng][0];
                    float d1 = c11 * (float)accP[mi][ng][1] + c12 * (float)accX[mi][ng][1];
                    float d2 = c11 * (float)accP[mi][ng][2] + c12 * (float)accX[mi][ng][2];
                    float d3 = c11 * (float)accP[mi][ng][3] + c12 * (float)accX[mi][ng][3];
                    float2 p0, p1;
                    p0.x = sqc[col] - 2.0f * d0;  p0.y = sqc[col + 1] - 2.0f * d1;
                    p1.x = sqc[col] - 2.0f * d2;  p1.y = sqc[col + 1] - 2.0f * d3;
                    *(float2*)(sm + SM_STG + (r0 * 66 + col) * 4) = p0;
                    *(float2*)(sm + SM_STG + ((r0 + 8) * 66 + col) * 4) = p1;
                }
            }
        }
        __syncthreads();

        // ---- exact self-entry: global col == global row ----
        if (tid < 64) {
            int cg = col0 + t * 64 + tid;
            int rl = cg - row0;
            if (rl >= 0 && rl < 128)
                *(float*)(sm + SM_STG + (rl * 66 + tid) * 4) =
                    -((const float*)(sm + SM_SQR))[rl];
        }
        __syncthreads();

        // ---- row scan: 2 threads/row x 32 cols, accumulate into reg top-6 ----
        {
            int r = tid >> 1, sh = tid & 1;
            int cgl = col0 + t * 64 + sh * 32;
            #pragma unroll
            for (int i = 0; i < 16; i++) {
                float2 v = *(const float2*)(sm + SM_STG + (r * 66 + sh * 32 + 2 * i) * 4);
                ins6(v.x, cgl + 2 * i, nb, ni);
                ins6(v.y, cgl + 2 * i + 1, nb, ni);
            }
        }
        __syncthreads();       // STG reuse next tile / final lists
    }

    // ---- final: merge 2 lists per row, write one slot ----
    {
        float* lists = (float*)(sm + SM_LST);
        #pragma unroll
        for (int k = 0; k < 6; k++) {
            lists[tid * 12 + k] = nb[k];
            lists[tid * 12 + 6 + k] = __int_as_float(ni[k]);
        }
    }
    __syncthreads();
    if (tid < 128) {
        const float* lists = (const float*)(sm + SM_LST);
        float mb[6]; int mi_[6];
        #pragma unroll
        for (int k = 0; k < 6; k++) { mb[k] = 3.0e38f; mi_[k] = 0; }
        #pragma unroll
        for (int s = 0; s < 2; s++) {
            const float* L = lists + (2 * tid + s) * 12;
            #pragma unroll
            for (int k = 0; k < 6; k++)
                ins6(L[k], __float_as_int(L[6 + k]), mb, mi_);
        }
        float2* dst = g_top + ((size_t)(row0 + tid) * 16 + bx) * 6;
        #pragma unroll
        for (int k = 0; k < 6; k++) {
            float2 p; p.x = mb[k]; p.y = __int_as_float(mi_[k]);
            dst[k] = p;
        }
    }
}

// ---------------- kernel 3: merge 16 slots/row, weights, scatter --------------
__global__ __launch_bounds__(256) void merge_scatter_kernel(float* __restrict__ out) {
    int warp = threadIdx.x >> 5, l = threadIdx.x & 31;
    int r = blockIdx.x * 8 + warp;

    float nb[6]; int ni[6];
    #pragma unroll
    for (int k = 0; k < 6; k++) { nb[k] = 3.0e38f; ni[k] = 0; }

    const float2* base = g_top + (size_t)r * 96;     // 16 slots x 6
    #pragma unroll
    for (int e = 0; e < 3; e++) {
        float2 p = base[l * 3 + e];
        ins6(p.x, __float_as_int(p.y), nb, ni);
    }
    #pragma unroll
    for (int off = 16; off; off >>= 1) {
        float tv[6]; int ti[6];
        #pragma unroll
        for (int k = 0; k < 6; k++) {
            tv[k] = __shfl_xor_sync(0xffffffffu, nb[k], off);
            ti[k] = __shfl_xor_sync(0xffffffffu, ni[k], off);
        }
        #pragma unroll
        for (int k = 0; k < 6; k++) ins6(tv[k], ti[k], nb, ni);
    }

    if (l == 0) {
        float sq_r = g_sq[r];
        float d[6];
        #pragma unroll
        for (int k = 0; k < 6; k++) d[k] = sqrtf(fmaxf(sq_r + nb[k], 1e-30f));
        float thr = d[5];
        float wv[6]; float norm = 0.0f;
        #pragma unroll
        for (int k = 0; k < 6; k++) { wv[k] = thr - d[k] + 1e-10f; norm += wv[k]; }
        float inv = 1.0f / fmaxf(norm, 1e-12f);
        #pragma unroll
        for (int k = 0; k < 6; k++)
            out[(size_t)r * NPTS + ni[k]] = wv[k] * inv;
    }
}

// ---------------- launch ------------------------------------------------------
extern "C" void kernel_launch(void* const* d_in, const int* in_sizes, int n_in,
                              void* d_out, int out_size) {
    const float* features = (const float*)d_in[0];
    float* out = (float*)d_out;
    (void)in_sizes; (void)n_in; (void)out_size;

    cudaFuncSetAttribute(gemm_topk_kernel,
                         cudaFuncAttributeMaxDynamicSharedMemorySize, SM_TOTAL);

    prep_kernel<<<NPTS / 8, 256>>>(features);
    gemm_topk_kernel<<<dim3(16, 64), 256, SM_TOTAL>>>(out);
    merge_scatter_kernel<<<NPTS / 8, 256>>>(out);
}

// round 8
// speedup vs baseline: 2.0282x; 2.0282x over previous
#include <cuda_runtime.h>
#include <cuda_fp16.h>
#include <cstdint>

#define NPTS 8192
#define DIM  128
#define NTILES2 4160           // 2080 triangle tiles x 2 column halves

// ---------------- scratch -----------------------------------------------------
static __device__ __half g_fh[(size_t)NPTS * DIM];        // fp16 features
static __device__ float  g_sq[NPTS];                      // exact fp32 row norms
static __device__ float2 g_top[(size_t)NPTS * 128 * 6];   // per-row 128 slot lists

// ---------------- helpers ------------------------------------------------------
__device__ __forceinline__ uint32_t smem_u32(const void* p) {
    uint32_t a;
    asm("{ .reg .u64 t; cvta.to.shared.u64 t, %1; cvt.u32.u64 %0, t; }"
        : "=r"(a) : "l"(p));
    return a;
}
__device__ __forceinline__ void cp16(uint32_t dst, const void* src) {
    asm volatile("cp.async.cg.shared.global [%0], [%1], 16;"
                 :: "r"(dst), "l"(src) : "memory");
}
#define CP_COMMIT() asm volatile("cp.async.commit_group;" ::: "memory")
#define CP_WAIT0()  asm volatile("cp.async.wait_group 0;" ::: "memory")

__device__ __forceinline__ void ldsm_x4(uint32_t* r, uint32_t addr) {
    asm volatile("ldmatrix.sync.aligned.m8n8.x4.shared.b16 {%0,%1,%2,%3}, [%4];"
        : "=r"(r[0]), "=r"(r[1]), "=r"(r[2]), "=r"(r[3]) : "r"(addr));
}
__device__ __forceinline__ void mma16816(float* c, const uint32_t* a,
                                         uint32_t b0, uint32_t b1) {
    asm volatile("mma.sync.aligned.m16n8k16.row.col.f32.f16.f16.f32 "
        "{%0,%1,%2,%3}, {%4,%5,%6,%7}, {%8,%9}, {%0,%1,%2,%3};"
        : "+f"(c[0]), "+f"(c[1]), "+f"(c[2]), "+f"(c[3])
        : "r"(a[0]), "r"(a[1]), "r"(a[2]), "r"(a[3]), "r"(b0), "r"(b1));
}

// swizzled byte offset inside a tile with 256B rows (16 chunks of 16B)
__device__ __forceinline__ uint32_t swz(int row, int chunk) {
    return (uint32_t)(row * 256 + (((chunk ^ row) & 7) | (chunk & 8)) * 16);
}

// top-6 insert (value + index), ascending
__device__ __forceinline__ void ins6(float v, int idx, float* nb, int* ni) {
    if (v < nb[5]) {
        nb[5] = v; ni[5] = idx;
        #pragma unroll
        for (int k = 5; k > 0; k--) {
            if (nb[k] < nb[k - 1]) {
                float tv = nb[k]; nb[k] = nb[k - 1]; nb[k - 1] = tv;
                int   ti = ni[k]; ni[k] = ni[k - 1]; ni[k - 1] = ti;
            }
        }
    }
}

// ---------------- kernel 1: fp16 convert + exact row norms --------------------
__global__ __launch_bounds__(256) void prep_kernel(const float* __restrict__ f) {
    int wid = threadIdx.x >> 5, lane = threadIdx.x & 31;
    int row = blockIdx.x * 8 + wid;
    float4 v = ((const float4*)f)[row * 32 + lane];
    float s = v.x * v.x + v.y * v.y + v.z * v.z + v.w * v.w;
    __half2 h0 = __floats2half2_rn(v.x, v.y);
    __half2 h1 = __floats2half2_rn(v.z, v.w);
    uint2 u;
    u.x = *(uint32_t*)&h0; u.y = *(uint32_t*)&h1;
    *(uint2*)(g_fh + (size_t)row * DIM + lane * 4) = u;
    #pragma unroll
    for (int o = 16; o; o >>= 1) s += __shfl_xor_sync(0xffffffffu, s, o);
    if (lane == 0) g_sq[row] = s;
}

// ---------------- kernel 2: 128x64 symmetric fp16 tile + row/col top-6 --------
// smem layout (bytes):
#define SM_A   0                           // 128 x 256 = 32768
#define SM_B   32768                       // 64 x 256  = 16384
#define SM_STG 49152                       // 128 x 66 words = 33792
#define SM_SQC 82944                       // 64 floats
#define SM_SQR 83200                       // 128 floats
#define SM_LST 83712                       // 256 x 12 floats = 12288
#define SM_TOTAL 96000

__global__ __launch_bounds__(256, 2)
void gemm_topk_kernel(float* __restrict__ out) {
    extern __shared__ char smem_[];
    char* sm = smem_;
    uint32_t sbase = smem_u32(sm);
    int tid = threadIdx.x;
    int b = blockIdx.x;
    int b2 = b >> 1, h = b & 1;

    // triangular decode: b2 -> (I <= J)
    int bi = (int)((sqrtf(8.0f * (float)b2 + 1.0f) - 1.0f) * 0.5f);
    while ((bi + 1) * (bi + 2) / 2 <= b2) bi++;
    while (bi * (bi + 1) / 2 > b2) bi--;
    int J = bi, I = b2 - bi * (bi + 1) / 2;
    bool diag = (I == J);

    if (tid < 64)       ((float*)(sm + SM_SQC))[tid] = g_sq[J * 128 + h * 64 + tid];
    else if (tid < 192) ((float*)(sm + SM_SQR))[tid - 64] = g_sq[I * 128 + (tid - 64)];

    // ---- async fills ----
    {
        // A: 128 rows x 16 chunks = 2048 cp16
        const char* a = (const char*)(g_fh + (size_t)(I * 128) * DIM);
        #pragma unroll
        for (int it = 0; it < 8; it++) {
            int idx = tid + it * 256;              // 0..2047
            int row = idx >> 4, ch = idx & 15;
            cp16(sbase + SM_A + swz(row, ch), a + (size_t)row * 256 + ch * 16);
        }
        if (!diag) {
            // B: 64 rows x 16 chunks = 1024 cp16
            const char* bp = (const char*)(g_fh + (size_t)(J * 128 + h * 64) * DIM);
            #pragma unroll
            for (int it = 0; it < 4; it++) {
                int idx = tid + it * 256;          // 0..1023
                int row = idx >> 4, ch = idx & 15;
                cp16(sbase + SM_B + swz(row, ch), bp + (size_t)row * 256 + ch * 16);
            }
        }
        CP_COMMIT();
    }

    // ---- zero-fill slice of out (overlaps cp.async latency) ----
    {
        float4 z = make_float4(0.f, 0.f, 0.f, 0.f);
        #pragma unroll
        for (int i = 0; i < 4; i++) {
            size_t gi = ((size_t)b * 4 + i) * 256 + tid;
            if (gi < (size_t)4194304) ((float4*)out)[gi] = z;
        }
    }

    CP_WAIT0();
    __syncthreads();

    // ---- fp16 HMMA mainloop: single chain, 8 k16-steps ----
    int wq = tid >> 5, l = tid & 31;
    int wm = wq & 3, wn = wq >> 2;            // 4x2 warps: 32-row x 32-col regions
    int lrow = (l & 7) | (((l >> 3) & 1) << 3);
    int kinc = (l >> 4) & 1;

    uint32_t Abase = sbase + SM_A;
    uint32_t Bbase = diag ? (Abase + h * 16384) : (sbase + SM_B);

    float acc[2][4][4];
    #pragma unroll
    for (int mi = 0; mi < 2; mi++)
        #pragma unroll
        for (int nf = 0; nf < 4; nf++)
            #pragma unroll
            for (int q = 0; q < 4; q++) acc[mi][nf][q] = 0.0f;

    #pragma unroll
    for (int ks = 0; ks < 8; ks++) {
        int ch = ks * 2 + kinc;
        uint32_t a[2][4];
        #pragma unroll
        for (int mi = 0; mi < 2; mi++)
            ldsm_x4(a[mi], Abase + swz(wm * 32 + mi * 16 + lrow, ch));
        uint32_t bb[2][4];
        #pragma unroll
        for (int ng = 0; ng < 2; ng++)
            ldsm_x4(bb[ng], Bbase + swz(wn * 32 + ng * 16 + lrow, ch));
        #pragma unroll
        for (int mi = 0; mi < 2; mi++)
            #pragma unroll
            for (int ng = 0; ng < 2; ng++) {
                mma16816(acc[mi][ng * 2 + 0], a[mi], bb[ng][0], bb[ng][2]);
                mma16816(acc[mi][ng * 2 + 1], a[mi], bb[ng][1], bb[ng][3]);
            }
    }

    // ---- stage s = sq_col - 2*dot into SM_STG (stride 66 words) ----
    {
        const float* sqc = (const float*)(sm + SM_SQC);
        #pragma unroll
        for (int mi = 0; mi < 2; mi++) {
            int r0 = wm * 32 + mi * 16 + (l >> 2);
            #pragma unroll
            for (int nf = 0; nf < 4; nf++) {
                int col = wn * 32 + nf * 8 + 2 * (l & 3);
                float2 p0, p1;
                p0.x = sqc[col]     - 2.0f * acc[mi][nf][0];
                p0.y = sqc[col + 1] - 2.0f * acc[mi][nf][1];
                p1.x = sqc[col]     - 2.0f * acc[mi][nf][2];
                p1.y = sqc[col + 1] - 2.0f * acc[mi][nf][3];
                *(float2*)(sm + SM_STG + (r0 * 66 + col) * 4) = p0;
                *(float2*)(sm + SM_STG + ((r0 + 8) * 66 + col) * 4) = p1;
            }
        }
    }
    __syncthreads();

    // ---- exact self-entry on diagonal tiles: force d_self^2 = 0 ----
    if (diag && tid < 64) {
        int rr = h * 64 + tid;
        *(float*)(sm + SM_STG + (rr * 66 + tid) * 4) =
            -((const float*)(sm + SM_SQR))[rr];
    }
    __syncthreads();

    const float* sqc = (const float*)(sm + SM_SQC);
    const float* sqr = (const float*)(sm + SM_SQR);
    float* lists = (float*)(sm + SM_LST);

    // ---- row scan: 2 threads per row, 32 cols each ----
    {
        int r = tid >> 1, sh = tid & 1;
        float nb[6]; int ni[6];
        #pragma unroll
        for (int k = 0; k < 6; k++) { nb[k] = 3.0e38f; ni[k] = 0; }
        int cgl = J * 128 + h * 64 + sh * 32;
        #pragma unroll
        for (int i = 0; i < 16; i++) {
            float2 v = *(const float2*)(sm + SM_STG + (r * 66 + sh * 32 + 2 * i) * 4);
            ins6(v.x, cgl + 2 * i, nb, ni);
            ins6(v.y, cgl + 2 * i + 1, nb, ni);
        }
        #pragma unroll
        for (int k = 0; k < 6; k++) {
            lists[tid * 12 + k] = nb[k];
            lists[tid * 12 + 6 + k] = __int_as_float(ni[k]);
        }
    }
    __syncthreads();
    if (tid < 128) {
        float mb[6]; int mi_[6];
        #pragma unroll
        for (int k = 0; k < 6; k++) { mb[k] = 3.0e38f; mi_[k] = 0; }
        #pragma unroll
        for (int s = 0; s < 2; s++) {
            const float* L = lists + (2 * tid + s) * 12;
            #pragma unroll
            for (int k = 0; k < 6; k++)
                ins6(L[k], __float_as_int(L[6 + k]), mb, mi_);
        }
        float2* dst = g_top + ((size_t)(I * 128 + tid) * 128 + (2 * J + h)) * 6;
        #pragma unroll
        for (int k = 0; k < 6; k++) {
            float2 p; p.x = mb[k]; p.y = __int_as_float(mi_[k]);
            dst[k] = p;
        }
    }

    // ---- col scan (skip on diagonal): 4 threads per col, 32 rows each ----
    if (!diag) {
        __syncthreads();
        {
            int c = tid & 63, q = tid >> 6;
            float sjc = sqc[c];
            float nb[6]; int ni[6];
            #pragma unroll
            for (int k = 0; k < 6; k++) { nb[k] = 3.0e38f; ni[k] = 0; }
            int rbase = q * 32;
            #pragma unroll
            for (int i = 0; i < 32; i++) {
                int rr = rbase + i;
                float sv = *(const float*)(sm + SM_STG + (rr * 66 + c) * 4);
                ins6(sv - sjc + sqr[rr], I * 128 + rr, nb, ni);
            }
            #pragma unroll
            for (int k = 0; k < 6; k++) {
                lists[tid * 12 + k] = nb[k];
                lists[tid * 12 + 6 + k] = __int_as_float(ni[k]);
            }
        }
        __syncthreads();
        if (tid < 64) {
            float mb[6]; int mi_[6];
            #pragma unroll
            for (int k = 0; k < 6; k++) { mb[k] = 3.0e38f; mi_[k] = 0; }
            #pragma unroll
            for (int s = 0; s < 4; s++) {
                const float* L = lists + (s * 64 + tid) * 12;
                #pragma unroll
                for (int k = 0; k < 6; k++)
                    ins6(L[k], __float_as_int(L[6 + k]), mb, mi_);
            }
            float2* dst = g_top + ((size_t)(J * 128 + h * 64 + tid) * 128 + (2 * I + h)) * 6;
            #pragma unroll
            for (int k = 0; k < 6; k++) {
                float2 p; p.x = mb[k]; p.y = __int_as_float(mi_[k]);
                dst[k] = p;
            }
        }
    }
}

// ---------------- kernel 3: merge valid slots, weights, scatter ---------------
__global__ __launch_bounds__(256) void merge_scatter_kernel(float* __restrict__ out) {
    int warp = threadIdx.x >> 5, l = threadIdx.x & 31;
    int r = blockIdx.x * 8 + warp;
    int J = r >> 7, hr = (r >> 6) & 1;

    float nb[6]; int ni[6];
    #pragma unroll
    for (int k = 0; k < 6; k++) { nb[k] = 3.0e38f; ni[k] = 0; }

    const float2* base = g_top + (size_t)r * 128 * 6;
    #pragma unroll
    for (int it = 0; it < 4; it++) {
        int s = l + it * 32;
        bool valid = (s >= 2 * J) || ((s & 1) == hr);
        if (valid) {
            const float4* p = (const float4*)(base + (size_t)s * 6);
            float4 p0 = p[0], p1 = p[1], p2 = p[2];
            ins6(p0.x, __float_as_int(p0.y), nb, ni);
            ins6(p0.z, __float_as_int(p0.w), nb, ni);
            ins6(p1.x, __float_as_int(p1.y), nb, ni);
            ins6(p1.z, __float_as_int(p1.w), nb, ni);
            ins6(p2.x, __float_as_int(p2.y), nb, ni);
            ins6(p2.z, __float_as_int(p2.w), nb, ni);
        }
    }
    #pragma unroll
    for (int off = 16; off; off >>= 1) {
        float tv[6]; int ti[6];
        #pragma unroll
        for (int k = 0; k < 6; k++) {
            tv[k] = __shfl_xor_sync(0xffffffffu, nb[k], off);
            ti[k] = __shfl_xor_sync(0xffffffffu, ni[k], off);
        }
        #pragma unroll
        for (int k = 0; k < 6; k++) ins6(tv[k], ti[k], nb, ni);
    }

    if (l == 0) {
        float sq_r = g_sq[r];
        float d[6];
        #pragma unroll
        for (int k = 0; k < 6; k++) d[k] = sqrtf(fmaxf(sq_r + nb[k], 1e-30f));
        float thr = d[5];
        float wv[6]; float norm = 0.0f;
        #pragma unroll
        for (int k = 0; k < 6; k++) { wv[k] = thr - d[k] + 1e-10f; norm += wv[k]; }
        float inv = 1.0f / fmaxf(norm, 1e-12f);
        #pragma unroll
        for (int k = 0; k < 6; k++)
            out[(size_t)r * NPTS + ni[k]] = wv[k] * inv;
    }
}

// ---------------- launch ------------------------------------------------------
extern "C" void kernel_launch(void* const* d_in, const int* in_sizes, int n_in,
                              void* d_out, int out_size) {
    const float* features = (const float*)d_in[0];
    float* out = (float*)d_out;
    (void)in_sizes; (void)n_in; (void)out_size;

    cudaFuncSetAttribute(gemm_topk_kernel,
                         cudaFuncAttributeMaxDynamicSharedMemorySize, SM_TOTAL);

    prep_kernel<<<NPTS / 8, 256>>>(features);
    gemm_topk_kernel<<<NTILES2, 256, SM_TOTAL>>>(out);
    merge_scatter_kernel<<<NPTS / 8, 256>>>(out);
}